// round 4
// baseline (speedup 1.0000x reference)
#include <cuda_runtime.h>

// Bilateral slice:
//   bilateral_grid: (N=4, C=12, GD=8, GH=16, GW=16) f32
//   guidemap:       (N=4, 1, H=1024, W=1024) f32
//   out:            (N=4, C=12, H=1024, W=1024) f32
//
// Design: one CTA per (n, y) output row. Since W/GW = H/GH = 64 exactly, the
// x-bilinear is piecewise-linear with 17 segments per row (m = (x+32)>>6),
// and the y-weights are fixed per row. Precompute per (c, segment m, z):
//   v(x) = P + Q * fracx     (y-interp already folded in)
// packed as float4 {P(z),Q(z),P(z+1 clamped),Q(z+1 clamped)} in shared.
// Each pixel then needs 1 LDS.128 + 4 FMA per channel (vs 8 LDG naive).

#define NB 4
#define CC 12
#define GD 8
#define GH 16
#define GW 16
#define HH 1024
#define WW 1024
#define NSEG 17            // segments per row: m = (x+32)>>6, m in [0,16]

__global__ __launch_bounds__(256) void slice_kernel(
    const float* __restrict__ grid,     // (N,C,GD,GH,GW)
    const float* __restrict__ guide,    // (N,1,H,W)
    float* __restrict__ out)            // (N,C,H,W)
{
    __shared__ float  rows[CC * GD * 2 * GW];   // [c][z][yy][x]  3072 f = 12 KB
    __shared__ float4 tab[CC * NSEG * GD];      // [c][m][z]      1632 f4 = 25.5 KB

    const int y = blockIdx.x;
    const int n = blockIdx.y;
    const int t = threadIdx.x;

    // ---- y interpolation setup (identical across block) ----
    const float ysf   = (y + 0.5f) * (1.0f / 64.0f);
    const float fyf   = floorf(ysf - 0.5f);
    const float fracy = ysf - 0.5f - fyf;
    const int   fy    = (int)fyf;
    const int   cy0   = min(max(fy, 0), GH - 1);
    const int   cy1   = min(max(fy + 1, 0), GH - 1);
    const float wy0   = 1.0f - fracy;
    const float wy1   = fracy;

    // ---- Phase A: pull the two needed y-rows of the grid into shared ----
    // rows[i], i = ((c*GD + z)*2 + yy)*GW + xw
    const float* gbase = grid + (size_t)n * (CC * GD * GH * GW);
    for (int i = t; i < CC * GD * 2 * GW; i += 256) {
        int xw  = i & (GW - 1);
        int yy  = (i >> 4) & 1;
        int cz  = i >> 5;                 // c*GD + z  (0..95)
        int cyy = yy ? cy1 : cy0;
        rows[i] = gbase[cz * (GH * GW) + cyy * GW + xw];
    }
    __syncthreads();

    // ---- Phase B: build affine table per (c, m, z) ----
    for (int idx = t; idx < CC * NSEG * GD; idx += 256) {
        int z  = idx & (GD - 1);
        int cm = idx >> 3;                // c*NSEG + m
        int m  = cm % NSEG;
        int c  = cm / NSEG;
        int z1  = min(z + 1, GD - 1);
        int cxa = max(m - 1, 0);
        int cxb = min(m, GW - 1);
        const float* r0 = rows + (c * GD + z)  * (2 * GW);
        const float* r1 = rows + (c * GD + z1) * (2 * GW);
        float A0 = wy0 * r0[cxa] + wy1 * r0[GW + cxa];
        float B0 = wy0 * r0[cxb] + wy1 * r0[GW + cxb];
        float A1 = wy0 * r1[cxa] + wy1 * r1[GW + cxa];
        float B1 = wy0 * r1[cxb] + wy1 * r1[GW + cxb];
        tab[idx] = make_float4(A0, B0 - A0, A1, B1 - A1);
    }
    __syncthreads();

    // ---- Main: each thread handles 4 consecutive x pixels (float4 I/O) ----
    const int x0 = t * 4;
    const int m  = (x0 + 32) >> 6;        // 4-px groups never straddle a segment

    const float4 g4 = *(const float4*)(guide + ((size_t)n * HH + y) * WW + x0);
    const float gv[4] = { g4.x, g4.y, g4.z, g4.w };

    float w0[4], w1[4], a0[4], a1[4];
    int   zi[4];
#pragma unroll
    for (int j = 0; j < 4; j++) {
        float fracx = (x0 + j + 0.5f) * (1.0f / 64.0f) + 0.5f - (float)m;  // [0,1)
        float zs    = gv[j] * (float)GD;
        float fzf   = floorf(zs - 0.5f);
        float fracz = zs - 0.5f - fzf;
        int   fz    = (int)fzf;
        if (fz < 0)      { fracz = 0.0f; fz = 0; }   // both z-taps clamp to 0
        if (fz > GD - 1) { fz = GD - 1; }            // both z-taps clamp to 7
        zi[j] = fz;
        w1[j] = fracz;
        w0[j] = 1.0f - fracz;
        a0[j] = w0[j] * fracx;
        a1[j] = w1[j] * fracx;
    }

    float* obase = out + (((size_t)n * CC) * HH + y) * WW + x0;
#pragma unroll
    for (int c = 0; c < CC; c++) {
        const float4* tbase = &tab[(c * NSEG + m) * GD];
        float r[4];
#pragma unroll
        for (int j = 0; j < 4; j++) {
            float4 e = tbase[zi[j]];
            r[j] = e.x * w0[j] + e.y * a0[j] + e.z * w1[j] + e.w * a1[j];
        }
        *(float4*)(obase + (size_t)c * (HH * WW)) = make_float4(r[0], r[1], r[2], r[3]);
    }
}

extern "C" void kernel_launch(void* const* d_in, const int* in_sizes, int n_in,
                              void* d_out, int out_size) {
    const float* grid  = (const float*)d_in[0];   // bilateral_grid
    const float* guide = (const float*)d_in[1];   // guidemap
    float* out = (float*)d_out;
    dim3 blocks(HH, NB);
    slice_kernel<<<blocks, 256>>>(grid, guide, out);
}

// round 6
// speedup vs baseline: 1.1826x; 1.1826x over previous
#include <cuda_runtime.h>

// Bilateral slice:
//   bilateral_grid: (N=4, C=12, GD=8, GH=16, GW=16) f32
//   guidemap:       (N=4, 1, H=1024, W=1024) f32
//   out:            (N=4, C=12, H=1024, W=1024) f32
//
// One CTA per (n, y) row. x-bilinear is piecewise linear over 17 segments
// (m = (x+32)>>6). Per (c, m, z) build affine coeffs v = P + Q*fracx with the
// y-interp folded in. Two shared tables (float2, stride 8 per (c,m)):
//   tabA[c][m][z] = {P(z),        Q(z)}
//   tabB[c][m][z] = {P(min(z+1,7)), Q(min(z+1,7))}
// LDS.64 bank index = (16*(c*17+m) + 2*z) mod 32: m-parity splits a warp's
// lanes into disjoint bank halves -> near-conflict-free shared reads.

#define NB 4
#define CC 12
#define GD 8
#define GH 16
#define GW 16
#define HH 1024
#define WW 1024
#define NSEG 17

__global__ __launch_bounds__(256) void slice_kernel(
    const float* __restrict__ grid,     // (N,C,GD,GH,GW)
    const float* __restrict__ guide,    // (N,1,H,W)
    float* __restrict__ out)            // (N,C,H,W)
{
    __shared__ __align__(128) float2 tabA[CC * NSEG * GD];  // 13056 B
    __shared__ __align__(128) float2 tabB[CC * NSEG * GD];  // 13056 B

    const int y = blockIdx.x;
    const int n = blockIdx.y;
    const int t = threadIdx.x;

    // ---- y interpolation setup (uniform across block) ----
    const float ysf   = (y + 0.5f) * (1.0f / 64.0f);
    const float fyf   = floorf(ysf - 0.5f);
    const float fracy = ysf - 0.5f - fyf;
    const int   fy    = (int)fyf;
    const int   cy0   = min(max(fy, 0), GH - 1);
    const int   cy1   = min(max(fy + 1, 0), GH - 1);
    const float wy0   = 1.0f - fracy;
    const float wy1   = fracy;

    // ---- Build affine tables straight from L2-resident grid ----
    const float* gbase = grid + (size_t)n * (CC * GD * GH * GW);
    for (int idx = t; idx < CC * NSEG * GD; idx += 256) {
        int z  = idx & (GD - 1);
        int cm = idx >> 3;                 // c*NSEG + m
        int m  = cm % NSEG;
        int c  = cm / NSEG;
        int z1  = min(z + 1, GD - 1);
        int cxa = max(m - 1, 0);
        int cxb = min(m, GW - 1);
        const float* g0 = gbase + (c * GD + z)  * (GH * GW);
        const float* g1 = gbase + (c * GD + z1) * (GH * GW);
        float A0 = wy0 * g0[cy0 * GW + cxa] + wy1 * g0[cy1 * GW + cxa];
        float B0 = wy0 * g0[cy0 * GW + cxb] + wy1 * g0[cy1 * GW + cxb];
        float A1 = wy0 * g1[cy0 * GW + cxa] + wy1 * g1[cy1 * GW + cxa];
        float B1 = wy0 * g1[cy0 * GW + cxb] + wy1 * g1[cy1 * GW + cxb];
        tabA[idx] = make_float2(A0, B0 - A0);
        tabB[idx] = make_float2(A1, B1 - A1);
    }
    __syncthreads();

    // ---- Main: 4 consecutive x pixels per thread (float4 I/O) ----
    const int x0 = t * 4;
    const int m  = (x0 + 32) >> 6;         // 4-px groups never straddle a segment

    const float4 g4 = *(const float4*)(guide + ((size_t)n * HH + y) * WW + x0);
    const float gv[4] = { g4.x, g4.y, g4.z, g4.w };

    float w0[4], w1[4], a0[4], a1[4];
    int   base[4];                          // m*8 + zi  (per-pixel table offset)
#pragma unroll
    for (int j = 0; j < 4; j++) {
        float fracx = (x0 + j + 0.5f) * (1.0f / 64.0f) + 0.5f - (float)m;  // [0,1)
        float zs    = gv[j] * (float)GD;
        float fzf   = floorf(zs - 0.5f);
        float fracz = zs - 0.5f - fzf;
        int   fz    = (int)fzf;
        if (fz < 0)      { fracz = 0.0f; fz = 0; }
        if (fz > GD - 1) { fz = GD - 1; }
        base[j] = m * GD + fz;
        w1[j] = fracz;
        w0[j] = 1.0f - fracz;
        a0[j] = w0[j] * fracx;
        a1[j] = w1[j] * fracx;
    }

    float* obase = out + (((size_t)n * CC) * HH + y) * WW + x0;
#pragma unroll
    for (int c = 0; c < CC; c++) {
        const int coff = c * (NSEG * GD);
        float r[4];
#pragma unroll
        for (int j = 0; j < 4; j++) {
            float2 e0 = tabA[coff + base[j]];
            float2 e1 = tabB[coff + base[j]];
            r[j] = e0.x * w0[j] + e0.y * a0[j] + e1.x * w1[j] + e1.y * a1[j];
        }
        *(float4*)(obase + (size_t)c * (HH * WW)) = make_float4(r[0], r[1], r[2], r[3]);
    }
}

extern "C" void kernel_launch(void* const* d_in, const int* in_sizes, int n_in,
                              void* d_out, int out_size) {
    const float* grid  = (const float*)d_in[0];   // bilateral_grid
    const float* guide = (const float*)d_in[1];   // guidemap
    float* out = (float*)d_out;
    dim3 blocks(HH, NB);
    slice_kernel<<<blocks, 256>>>(grid, guide, out);
}

// round 7
// speedup vs baseline: 1.4293x; 1.2086x over previous
#include <cuda_runtime.h>

// Bilateral slice:
//   bilateral_grid: (N=4, C=12, GD=8, GH=16, GW=16) f32
//   guidemap:       (N=4, 1, H=1024, W=1024) f32
//   out:            (N=4, C=12, H=1024, W=1024) f32
//
// One CTA (512 threads) per (n, y) row. x-bilinear is piecewise linear over 17
// segments (m = (x+32)>>6). Per (c, m, z): affine coeffs with y-interp folded:
//   tab[c][m][z] = {P(z), Q(z), P(min(z+1,7)), Q(min(z+1,7))}   (float4)
//   value = wz0*(P + Q*fx) + wz1*(P' + Q'*fx)
// Warp<->pixel mapping makes m UNIFORM per warp instruction:
//   warp u (u=1..15) owns the 64-px window [64u-32, 64u+31]  (m = u)
//   warp 0 owns [0,31] (m=0, lanes 0-15) + [992,1023] (m=16, lanes 16-31)
// => LDS.128 bank group = (z + const) mod 8: conflict-free gather.

#define NB 4
#define CC 12
#define GD 8
#define GH 16
#define GW 16
#define HH 1024
#define WW 1024
#define NSEG 17
#define RSTRIDE 34   // rows: per (c,z): [yy][17] padded -> bank-conflict-free build

__global__ __launch_bounds__(512) void slice_kernel(
    const float* __restrict__ grid,     // (N,C,GD,GH,GW)
    const float* __restrict__ guide,    // (N,1,H,W)
    float* __restrict__ out)            // (N,C,H,W)
{
    __shared__ float  rows[CC * GD * RSTRIDE];          // 3264 f = 12.75 KB
    __shared__ __align__(128) float4 tab[CC * NSEG * GD];  // 1632 f4 = 25.5 KB

    const int y = blockIdx.x;
    const int n = blockIdx.y;
    const int t = threadIdx.x;

    // ---- y interpolation setup (uniform across block) ----
    const float ysf   = (y + 0.5f) * (1.0f / 64.0f);
    const float fyf   = floorf(ysf - 0.5f);
    const float fracy = ysf - 0.5f - fyf;
    const int   fy    = (int)fyf;
    const int   cy0   = min(max(fy, 0), GH - 1);
    const int   cy1   = min(max(fy + 1, 0), GH - 1);
    const float wy0   = 1.0f - fracy;
    const float wy1   = fracy;

    // ---- Phase A: stage the two needed grid y-rows (coalesced LDG) ----
    const float* gbase = grid + (size_t)n * (CC * GD * GH * GW);
    for (int i = t; i < CC * GD * 2 * GW; i += 512) {
        int xw  = i & 15;
        int yy  = (i >> 4) & 1;
        int cz  = i >> 5;                       // c*GD + z, 0..95
        int cyy = yy ? cy1 : cy0;
        rows[cz * RSTRIDE + yy * 17 + xw] = gbase[cz * (GH * GW) + cyy * GW + xw];
    }
    __syncthreads();

    // ---- Phase B: build affine table from shared ----
    for (int idx = t; idx < CC * NSEG * GD; idx += 512) {
        int z  = idx & (GD - 1);
        int cm = idx >> 3;                      // c*NSEG + m
        int m  = cm % NSEG;
        int c  = cm / NSEG;
        int z1  = min(z + 1, GD - 1);
        int cxa = max(m - 1, 0);
        int cxb = min(m, GW - 1);
        const float* r0 = rows + (c * GD + z)  * RSTRIDE;
        const float* r1 = rows + (c * GD + z1) * RSTRIDE;
        float A0 = wy0 * r0[cxa] + wy1 * r0[17 + cxa];
        float B0 = wy0 * r0[cxb] + wy1 * r0[17 + cxb];
        float A1 = wy0 * r1[cxa] + wy1 * r1[17 + cxa];
        float B1 = wy0 * r1[cxb] + wy1 * r1[17 + cxb];
        tab[idx] = make_float4(A0, B0 - A0, A1, B1 - A1);
    }
    __syncthreads();

    // ---- Warp->segment mapping: m uniform per warp instruction ----
    const int u = t >> 5;
    const int l = t & 31;
    int m, xb;
    if (u == 0) {
        m  = (l < 16) ? 0 : 16;
        xb = (l < 16) ? (2 * l) : (960 + 2 * l);   // [0,31] / [992,1023]
    } else {
        m  = u;
        xb = 64 * u - 32 + 2 * l;                   // 64-px window, 2 px/lane
    }

    const float2 g2 = *(const float2*)(guide + ((size_t)n * HH + y) * WW + xb);
    const float gv[2] = { g2.x, g2.y };

    float w0[2], w1[2], a0[2], a1[2];
    int   bs[2];
#pragma unroll
    for (int j = 0; j < 2; j++) {
        float fracx = (xb + j + 0.5f) * (1.0f / 64.0f) + 0.5f - (float)m;  // [0,1)
        float zs    = gv[j] * (float)GD;
        float fzf   = floorf(zs - 0.5f);
        float fracz = zs - 0.5f - fzf;
        int   fz    = (int)fzf;
        if (fz < 0)      { fracz = 0.0f; fz = 0; }
        if (fz > GD - 1) { fz = GD - 1; }
        bs[j] = m * GD + fz;
        w1[j] = fracz;
        w0[j] = 1.0f - fracz;
        a0[j] = w0[j] * fracx;
        a1[j] = w1[j] * fracx;
    }

    float* obase = out + (((size_t)n * CC) * HH + y) * WW + xb;
#pragma unroll
    for (int c = 0; c < CC; c++) {
        const float4* tb = tab + c * (NSEG * GD);
        float r[2];
#pragma unroll
        for (int j = 0; j < 2; j++) {
            float4 e = tb[bs[j]];
            r[j] = e.x * w0[j] + e.y * a0[j] + e.z * w1[j] + e.w * a1[j];
        }
        *(float2*)(obase + (size_t)c * (HH * WW)) = make_float2(r[0], r[1]);
    }
}

extern "C" void kernel_launch(void* const* d_in, const int* in_sizes, int n_in,
                              void* d_out, int out_size) {
    const float* grid  = (const float*)d_in[0];   // bilateral_grid
    const float* guide = (const float*)d_in[1];   // guidemap
    float* out = (float*)d_out;
    dim3 blocks(HH, NB);
    slice_kernel<<<blocks, 512>>>(grid, guide, out);
}

// round 9
// speedup vs baseline: 1.7367x; 1.2151x over previous
#include <cuda_runtime.h>

// Bilateral slice:
//   bilateral_grid: (N=4, C=12, GD=8, GH=16, GW=16) f32
//   guidemap:       (N=4, 1, H=1024, W=1024) f32
//   out:            (N=4, C=12, H=1024, W=1024) f32
//
// One CTA (512 threads) per (n, y) row.
//   Phase 1: yr[c][z][x] = wy0*grid[..cy0..x] + wy1*grid[..cy1..x]
//            (y-interp folded once; built straight from L2-resident grid)
//   Phase 2: tab[c][m][z] = {P(z), Q(z), P(z1), Q(z1)} affine-in-fracx coeffs
//            (4 LDS + 1 STS per entry; adjacent m share yr values)
//   Main:    warp-uniform segment m; per pixel-channel ONE conflict-free
//            LDS.128 + 4 FMA:  v = P*wz0 + Q*(wz0*fx) + P'*wz1 + Q'*(wz1*fx)

#define NB 4
#define CC 12
#define GD 8
#define GH 16
#define GW 16
#define HH 1024
#define WW 1024
#define NSEG 17
#define YRS 17          // yr x-stride (16 values + 1 pad -> distinct banks per z)

__global__ __launch_bounds__(512) void slice_kernel(
    const float* __restrict__ grid,     // (N,C,GD,GH,GW)
    const float* __restrict__ guide,    // (N,1,H,W)
    float* __restrict__ out)            // (N,C,H,W)
{
    __shared__ float yr[CC * GD * YRS];                    // 6528 B
    __shared__ __align__(128) float4 tab[CC * NSEG * GD];  // 26112 B

    const int y = blockIdx.x;
    const int n = blockIdx.y;
    const int t = threadIdx.x;

    // ---- y interpolation setup (uniform across block) ----
    const float ysf   = (y + 0.5f) * (1.0f / 64.0f);
    const float fyf   = floorf(ysf - 0.5f);
    const float fracy = ysf - 0.5f - fyf;
    const int   fy    = (int)fyf;
    const int   cy0   = min(max(fy, 0), GH - 1);
    const int   cy1   = min(max(fy + 1, 0), GH - 1);
    const float wy0   = 1.0f - fracy;
    const float wy1   = fracy;

    // ---- Phase 1: y-interpolated grid rows, straight from global (L2 hits) ----
    const float* gbase = grid + (size_t)n * (CC * GD * GH * GW);
    for (int i = t; i < CC * GD * GW; i += 512) {          // 1536 entries, 3 iters
        int x  = i & (GW - 1);
        int cz = i >> 4;                                   // c*GD + z, 0..95
        const float* g = gbase + cz * (GH * GW);
        yr[cz * YRS + x] = wy0 * g[cy0 * GW + x] + wy1 * g[cy1 * GW + x];
    }
    __syncthreads();

    // ---- Phase 2: affine table (4 LDS + 1 STS.128 per entry) ----
    for (int idx = t; idx < CC * NSEG * GD; idx += 512) {  // 1632 entries
        int z  = idx & (GD - 1);
        int cm = idx >> 3;                                 // c*NSEG + m
        int m  = cm % NSEG;
        int c  = cm / NSEG;
        int z1  = min(z + 1, GD - 1);
        int cxa = max(m - 1, 0);
        int cxb = min(m, GW - 1);
        const float* y0 = yr + (c * GD + z)  * YRS;
        const float* y1 = yr + (c * GD + z1) * YRS;
        float A0 = y0[cxa], B0 = y0[cxb];
        float A1 = y1[cxa], B1 = y1[cxb];
        tab[idx] = make_float4(A0, B0 - A0, A1, B1 - A1);
    }
    __syncthreads();

    // ---- Warp->segment mapping: m uniform per warp instruction ----
    const int u = t >> 5;
    const int l = t & 31;
    int m, xb;
    if (u == 0) {
        m  = (l < 16) ? 0 : 16;
        xb = (l < 16) ? (2 * l) : (960 + 2 * l);   // [0,31] / [992,1023]
    } else {
        m  = u;
        xb = 64 * u - 32 + 2 * l;                   // 64-px window, 2 px/lane
    }

    const float2 g2 = *(const float2*)(guide + ((size_t)n * HH + y) * WW + xb);
    const float gv[2] = { g2.x, g2.y };

    float w0[2], w1[2], a0[2], a1[2];
    int   bs[2];
#pragma unroll
    for (int j = 0; j < 2; j++) {
        float fracx = (xb + j + 0.5f) * (1.0f / 64.0f) + 0.5f - (float)m;  // [0,1)
        float zs    = gv[j] * (float)GD;
        float fzf   = floorf(zs - 0.5f);
        float fracz = zs - 0.5f - fzf;
        int   fz    = (int)fzf;
        if (fz < 0)      { fracz = 0.0f; fz = 0; }
        if (fz > GD - 1) { fz = GD - 1; }
        bs[j] = m * GD + fz;
        w1[j] = fracz;
        w0[j] = 1.0f - fracz;
        a0[j] = w0[j] * fracx;
        a1[j] = w1[j] * fracx;
    }

    float* obase = out + (((size_t)n * CC) * HH + y) * WW + xb;
#pragma unroll
    for (int c = 0; c < CC; c++) {
        const float4* tb = tab + c * (NSEG * GD);
        float r[2];
#pragma unroll
        for (int j = 0; j < 2; j++) {
            float4 e = tb[bs[j]];
            r[j] = e.x * w0[j] + e.y * a0[j] + e.z * w1[j] + e.w * a1[j];
        }
        *(float2*)(obase + (size_t)c * (HH * WW)) = make_float2(r[0], r[1]);
    }
}

extern "C" void kernel_launch(void* const* d_in, const int* in_sizes, int n_in,
                              void* d_out, int out_size) {
    const float* grid  = (const float*)d_in[0];   // bilateral_grid
    const float* guide = (const float*)d_in[1];   // guidemap
    float* out = (float*)d_out;
    dim3 blocks(HH, NB);
    slice_kernel<<<blocks, 512>>>(grid, guide, out);
}

// round 13
// speedup vs baseline: 1.8446x; 1.0621x over previous
#include <cuda_runtime.h>

// Bilateral slice:
//   bilateral_grid: (N=4, C=12, GD=8, GH=16, GW=16) f32
//   guidemap:       (N=4, 1, H=1024, W=1024) f32
//   out:            (N=4, C=12, H=1024, W=1024) f32
//
// One CTA (512 threads) per (n, y) row.
//   Phase 1: yr[c][z][x] = wy0*grid[..cy0..x] + wy1*grid[..cy1..x]
//   Phase 2: tab[c][m][z] = {P, Q, P', Q'} affine-in-fracx coeffs (float4)
//   Main:    warp-uniform segment m; per pixel-channel ONE conflict-free
//            LDS.128 (immediate channel offset) + 4 FMA.
// __launch_bounds__(512, 4): force <=32 regs -> 4 CTAs/SM (100% occ ceiling).

#define NB 4
#define CC 12
#define GD 8
#define GH 16
#define GW 16
#define HH 1024
#define WW 1024
#define NSEG 17
#define YRS 17            // yr x-stride (16 + 1 pad)
#define CSTRIDE (NSEG * GD * 16)   // bytes per channel in tab: 2176

__global__ __launch_bounds__(512, 4) void slice_kernel(
    const float* __restrict__ grid,     // (N,C,GD,GH,GW)
    const float* __restrict__ guide,    // (N,1,H,W)
    float* __restrict__ out)            // (N,C,H,W)
{
    __shared__ float yr[CC * GD * YRS];                    // 6528 B
    __shared__ __align__(128) float4 tab[CC * NSEG * GD];  // 26112 B

    const int y = blockIdx.x;
    const int n = blockIdx.y;
    const int t = threadIdx.x;

    // ---- y interpolation setup (uniform across block) ----
    const float ysf   = (y + 0.5f) * (1.0f / 64.0f);
    const float fyf   = floorf(ysf - 0.5f);
    const float fracy = ysf - 0.5f - fyf;
    const int   fy    = (int)fyf;
    const int   cy0   = min(max(fy, 0), GH - 1);
    const int   cy1   = min(max(fy + 1, 0), GH - 1);
    const float wy0   = 1.0f - fracy;
    const float wy1   = fracy;

    // ---- Phase 1: y-interpolated grid rows from L2-resident global ----
    const float* gbase = grid + (size_t)n * (CC * GD * GH * GW);
    for (int i = t; i < CC * GD * GW; i += 512) {          // 1536 entries
        int x  = i & (GW - 1);
        int cz = i >> 4;                                   // c*GD + z
        const float* g = gbase + cz * (GH * GW);
        yr[cz * YRS + x] = wy0 * g[cy0 * GW + x] + wy1 * g[cy1 * GW + x];
    }
    __syncthreads();

    // ---- Phase 2: affine table (4 LDS + 1 STS.128 per entry) ----
    for (int idx = t; idx < CC * NSEG * GD; idx += 512) {  // 1632 entries
        int z  = idx & (GD - 1);
        int cm = idx >> 3;
        int m  = cm % NSEG;
        int c  = cm / NSEG;
        int z1  = min(z + 1, GD - 1);
        int cxa = max(m - 1, 0);
        int cxb = min(m, GW - 1);
        const float* y0 = yr + (c * GD + z)  * YRS;
        const float* y1 = yr + (c * GD + z1) * YRS;
        float A0 = y0[cxa], B0 = y0[cxb];
        float A1 = y1[cxa], B1 = y1[cxb];
        tab[idx] = make_float4(A0, B0 - A0, A1, B1 - A1);
    }
    __syncthreads();

    // ---- Warp->segment mapping: m uniform per warp instruction ----
    const int u = t >> 5;
    const int l = t & 31;
    int m, xb;
    if (u == 0) {
        m  = (l < 16) ? 0 : 16;
        xb = (l < 16) ? (2 * l) : (960 + 2 * l);   // [0,31] / [992,1023]
    } else {
        m  = u;
        xb = 64 * u - 32 + 2 * l;                   // 64-px window, 2 px/lane
    }

    const float2 g2 = *(const float2*)(guide + ((size_t)n * HH + y) * WW + xb);
    const float gv[2] = { g2.x, g2.y };

    float w0[2], w1[2], a0[2], a1[2];
    const char* tbase[2];                 // per-pixel byte base into tab
#pragma unroll
    for (int j = 0; j < 2; j++) {
        float fracx = (xb + j + 0.5f) * (1.0f / 64.0f) + 0.5f - (float)m;  // [0,1)
        float zs    = gv[j] * (float)GD;
        float fzf   = floorf(zs - 0.5f);
        float fracz = zs - 0.5f - fzf;
        int   fz    = (int)fzf;
        if (fz < 0)      { fracz = 0.0f; fz = 0; }
        if (fz > GD - 1) { fz = GD - 1; }
        tbase[j] = (const char*)tab + (m * GD + fz) * 16;
        w1[j] = fracz;
        w0[j] = 1.0f - fracz;
        a0[j] = w0[j] * fracx;
        a1[j] = w1[j] * fracx;
    }

    float* obase = out + (((size_t)n * CC) * HH + y) * WW + xb;
#pragma unroll
    for (int c = 0; c < CC; c++) {
        float r[2];
#pragma unroll
        for (int j = 0; j < 2; j++) {
            float4 e = *(const float4*)(tbase[j] + c * CSTRIDE);  // LDS [R+imm]
            r[j] = e.x * w0[j] + e.y * a0[j] + e.z * w1[j] + e.w * a1[j];
        }
        *(float2*)(obase + (size_t)c * (HH * WW)) = make_float2(r[0], r[1]);
    }
}

extern "C" void kernel_launch(void* const* d_in, const int* in_sizes, int n_in,
                              void* d_out, int out_size) {
    const float* grid  = (const float*)d_in[0];   // bilateral_grid
    const float* guide = (const float*)d_in[1];   // guidemap
    float* out = (float*)d_out;
    dim3 blocks(HH, NB);
    slice_kernel<<<blocks, 512>>>(grid, guide, out);
}

// round 14
// speedup vs baseline: 2.0459x; 1.1091x over previous
#include <cuda_runtime.h>
#include <cuda_fp16.h>

// Bilateral slice:
//   bilateral_grid: (N=4, C=12, GD=8, GH=16, GW=16) f32
//   guidemap:       (N=4, 1, H=1024, W=1024) f32
//   out:            (N=4, C=12, H=1024, W=1024) f32
//
// One CTA (512 threads) per (n, y) row.
//   Phase 1: yr[c][z][x] = wy0*grid[..cy0..x] + wy1*grid[..cy1..x]   (fp32)
//   Phase 2: tab[c][m][z] = {half2(P,Q), half2(P',Q')}  (8B/entry)
//   Main:    warp-uniform segment m; per pixel-channel ONE conflict-free
//            LDS.64 + 2 CVT + 4 FMA (fp32 accumulate).
// fp16 table halves shared-crossbar bytes (the measured L1 bottleneck).

#define NB 4
#define CC 12
#define GD 8
#define GH 16
#define GW 16
#define HH 1024
#define WW 1024
#define NSEG 17
#define YRS 17                      // yr x-stride (16 + 1 pad)
#define CSTRIDE (NSEG * GD * 8)     // bytes per channel in tab: 1088

__global__ __launch_bounds__(512, 4) void slice_kernel(
    const float* __restrict__ grid,     // (N,C,GD,GH,GW)
    const float* __restrict__ guide,    // (N,1,H,W)
    float* __restrict__ out)            // (N,C,H,W)
{
    __shared__ float yr[CC * GD * YRS];                    // 6528 B
    __shared__ __align__(128) uint2 tab[CC * NSEG * GD];   // 13056 B

    const int y = blockIdx.x;
    const int n = blockIdx.y;
    const int t = threadIdx.x;

    // ---- y interpolation setup (uniform across block) ----
    const float ysf   = (y + 0.5f) * (1.0f / 64.0f);
    const float fyf   = floorf(ysf - 0.5f);
    const float fracy = ysf - 0.5f - fyf;
    const int   fy    = (int)fyf;
    const int   cy0   = min(max(fy, 0), GH - 1);
    const int   cy1   = min(max(fy + 1, 0), GH - 1);
    const float wy0   = 1.0f - fracy;
    const float wy1   = fracy;

    // ---- Phase 1: y-interpolated grid rows from L2-resident global ----
    const float* gbase = grid + (size_t)n * (CC * GD * GH * GW);
    for (int i = t; i < CC * GD * GW; i += 512) {          // 1536 entries
        int x  = i & (GW - 1);
        int cz = i >> 4;                                   // c*GD + z
        const float* g = gbase + cz * (GH * GW);
        yr[cz * YRS + x] = wy0 * g[cy0 * GW + x] + wy1 * g[cy1 * GW + x];
    }
    __syncthreads();

    // ---- Phase 2: fp16 affine table (compute fp32, round once) ----
    for (int idx = t; idx < CC * NSEG * GD; idx += 512) {  // 1632 entries
        int z  = idx & (GD - 1);
        int cm = idx >> 3;
        int m  = cm % NSEG;
        int c  = cm / NSEG;
        int z1  = min(z + 1, GD - 1);
        int cxa = max(m - 1, 0);
        int cxb = min(m, GW - 1);
        const float* y0 = yr + (c * GD + z)  * YRS;
        const float* y1 = yr + (c * GD + z1) * YRS;
        float A0 = y0[cxa], B0 = y0[cxb];
        float A1 = y1[cxa], B1 = y1[cxb];
        __half2 lo = __floats2half2_rn(A0, B0 - A0);
        __half2 hi = __floats2half2_rn(A1, B1 - A1);
        tab[idx] = make_uint2(*(const unsigned*)&lo, *(const unsigned*)&hi);
    }
    __syncthreads();

    // ---- Warp->segment mapping: m uniform per warp instruction ----
    const int u = t >> 5;
    const int l = t & 31;
    int m, xb;
    if (u == 0) {
        m  = (l < 16) ? 0 : 16;
        xb = (l < 16) ? (2 * l) : (960 + 2 * l);   // [0,31] / [992,1023]
    } else {
        m  = u;
        xb = 64 * u - 32 + 2 * l;                   // 64-px window, 2 px/lane
    }

    const float2 g2 = *(const float2*)(guide + ((size_t)n * HH + y) * WW + xb);
    const float gv[2] = { g2.x, g2.y };

    float w0[2], w1[2], a0[2], a1[2];
    const char* tbase[2];                 // per-pixel byte base into tab
#pragma unroll
    for (int j = 0; j < 2; j++) {
        float fracx = (xb + j + 0.5f) * (1.0f / 64.0f) + 0.5f - (float)m;  // [0,1)
        float zs    = gv[j] * (float)GD;
        float fzf   = floorf(zs - 0.5f);
        float fracz = zs - 0.5f - fzf;
        int   fz    = (int)fzf;
        if (fz < 0)      { fracz = 0.0f; fz = 0; }
        if (fz > GD - 1) { fz = GD - 1; }
        tbase[j] = (const char*)tab + (m * GD + fz) * 8;
        w1[j] = fracz;
        w0[j] = 1.0f - fracz;
        a0[j] = w0[j] * fracx;
        a1[j] = w1[j] * fracx;
    }

    float* obase = out + (((size_t)n * CC) * HH + y) * WW + xb;
#pragma unroll
    for (int c = 0; c < CC; c++) {
        float r[2];
#pragma unroll
        for (int j = 0; j < 2; j++) {
            uint2 e = *(const uint2*)(tbase[j] + c * CSTRIDE);   // LDS.64
            float2 p0 = __half22float2(*(const __half2*)&e.x);   // {P,  Q }
            float2 p1 = __half22float2(*(const __half2*)&e.y);   // {P', Q'}
            r[j] = p0.x * w0[j] + p0.y * a0[j] + p1.x * w1[j] + p1.y * a1[j];
        }
        *(float2*)(obase + (size_t)c * (HH * WW)) = make_float2(r[0], r[1]);
    }
}

extern "C" void kernel_launch(void* const* d_in, const int* in_sizes, int n_in,
                              void* d_out, int out_size) {
    const float* grid  = (const float*)d_in[0];   // bilateral_grid
    const float* guide = (const float*)d_in[1];   // guidemap
    float* out = (float*)d_out;
    dim3 blocks(HH, NB);
    slice_kernel<<<blocks, 512>>>(grid, guide, out);
}